// round 7
// baseline (speedup 1.0000x reference)
#include <cuda_runtime.h>
#include <cuda_bf16.h>
#include <cuda_fp16.h>
#include <cstdint>
#include <math.h>

#define TT 256
#define BB 32
#define HH 1024
#define G4 4096
#define BH (BB*HH)
#define KC3 3072

// ---------------------------------------------------------------------------
// Static scratch (no cudaMalloc allowed)
// ---------------------------------------------------------------------------
__device__ __align__(16) float g_gates[(size_t)TT*BB*G4];          // 128 MB
__device__ __align__(16) float g_yf[BH];
__device__ __align__(16) __half g_y16[2][BH];                      // y fp16 double buffer
__device__ __align__(16) __nv_bfloat16 g_xcat[(size_t)TT*BB*KC3];
__device__ __align__(16) __nv_bfloat16 g_ycat[(size_t)TT*BB*KC3];
__device__ __align__(16) __nv_bfloat16 g_w0cat[(size_t)G4*KC3];
__device__ __align__(16) __nv_bfloat16 g_w1cat[(size_t)G4*KC3];
__device__ __align__(16) __half g_R0h[(size_t)G4*HH];              // blk-reordered fp16 hi
__device__ __align__(16) __half g_R0l[(size_t)G4*HH];              // residual * 2048
__device__ __align__(16) __half g_R1h[(size_t)G4*HH];
__device__ __align__(16) __half g_R1l[(size_t)G4*HH];

// per-block step flags (monotonic across launches/replays -> replay-safe)
__device__ unsigned g_yflag[128];

// ---------------------------------------------------------------------------
// PTX helpers (family-generic legal)
// ---------------------------------------------------------------------------
__device__ __forceinline__ uint32_t s2u(const void* p) {
    uint32_t a;
    asm("{ .reg .u64 t; cvta.to.shared.u64 t, %1; cvt.u32.u64 %0, t; }" : "=r"(a) : "l"(p));
    return a;
}
__device__ __forceinline__ void cp16(uint32_t saddr, const void* g) {
    asm volatile("cp.async.cg.shared.global [%0], [%1], 16;" :: "r"(saddr), "l"(g));
}
#define CP_COMMIT() asm volatile("cp.async.commit_group;" ::: "memory")
#define CP_WAIT1()  asm volatile("cp.async.wait_group 1;" ::: "memory")
#define CP_WAIT0()  asm volatile("cp.async.wait_group 0;" ::: "memory")

__device__ __forceinline__ void ldsm_x4(uint32_t* r, uint32_t addr) {
    asm volatile("ldmatrix.sync.aligned.m8n8.x4.shared.b16 {%0,%1,%2,%3}, [%4];"
        : "=r"(r[0]), "=r"(r[1]), "=r"(r[2]), "=r"(r[3]) : "r"(addr));
}
__device__ __forceinline__ void mma16816(float* d, const uint32_t* a, const uint32_t* b) {
    asm volatile("mma.sync.aligned.m16n8k16.row.col.f32.bf16.bf16.f32 "
        "{%0,%1,%2,%3}, {%4,%5,%6,%7}, {%8,%9}, {%0,%1,%2,%3};"
        : "+f"(d[0]), "+f"(d[1]), "+f"(d[2]), "+f"(d[3])
        : "r"(a[0]), "r"(a[1]), "r"(a[2]), "r"(a[3]), "r"(b[0]), "r"(b[1]));
}
__device__ __forceinline__ void mma16816h(float* d, const uint32_t* a, const uint32_t* b) {
    asm volatile("mma.sync.aligned.m16n8k16.row.col.f32.f16.f16.f32 "
        "{%0,%1,%2,%3}, {%4,%5,%6,%7}, {%8,%9}, {%0,%1,%2,%3};"
        : "+f"(d[0]), "+f"(d[1]), "+f"(d[2]), "+f"(d[3])
        : "r"(a[0]), "r"(a[1]), "r"(a[2]), "r"(a[3]), "r"(b[0]), "r"(b[1]));
}
__device__ __forceinline__ unsigned ld_acq(const unsigned* p) {
    unsigned v;
    asm volatile("ld.acquire.gpu.global.u32 %0, [%1];" : "=r"(v) : "l"(p));
    return v;
}
__device__ __forceinline__ void st_rel(unsigned* p, unsigned v) {
    asm volatile("st.release.gpu.global.u32 [%0], %1;" :: "l"(p), "r"(v));
}
__device__ __forceinline__ float fsig(float x) {
    return __fdividef(1.f, 1.f + __expf(-x));
}
__device__ __forceinline__ float ftanh(float x) {
    float e = __expf(-2.f * fabsf(x));
    float t = __fdividef(1.f - e, 1.f + e);
    return copysignf(t, x);
}

// ---------------------------------------------------------------------------
// Conversions
// ---------------------------------------------------------------------------
__global__ void split_cat(const float* __restrict__ src, __nv_bfloat16* __restrict__ dst,
                          size_t rows, int modeB) {
    size_t n = rows * HH;
    for (size_t i = (size_t)blockIdx.x * blockDim.x + threadIdx.x; i < n;
         i += (size_t)gridDim.x * blockDim.x) {
        size_t r = i >> 10; int k = (int)(i & 1023);
        float v = src[i];
        __nv_bfloat16 h = __float2bfloat16(v);
        __nv_bfloat16 l = __float2bfloat16(v - __bfloat162float(h));
        __nv_bfloat16* d = dst + r * KC3 + k;
        d[0] = h;
        d[1024] = modeB ? l : h;
        d[2048] = modeB ? h : l;
    }
}

// Reorder + fp16 split of R (dst row d = blk*32 + gate*8 + hl) and, in extra
// blocks, convert h0 slice into the fp16 y buffer 0.
__global__ void split_R16(const float* __restrict__ R, __half* __restrict__ hi,
                          __half* __restrict__ lo,
                          const float* __restrict__ h0p, __half* __restrict__ y0) {
    if (blockIdx.x < 2048) {
        size_t base = (size_t)blockIdx.x * 2048 + threadIdx.x;
        #pragma unroll
        for (int u = 0; u < 8; u++) {
            size_t i = base + (size_t)u * 256;
            int d = (int)(i >> 10), k = (int)(i & 1023);
            int blk = d >> 5, gate = (d >> 3) & 3, hl = d & 7;
            int srow = gate * HH + blk * 8 + hl;
            float v = R[(size_t)srow * HH + k];
            __half h = __float2half(v);
            hi[i] = h;
            lo[i] = __float2half((v - __half2float(h)) * 2048.0f);
        }
    } else {
        int base = (int)(blockIdx.x - 2048) * 1024 + threadIdx.x;
        #pragma unroll
        for (int u = 0; u < 4; u++) {
            int i = base + u * 256;
            y0[i] = __float2half(h0p[i]);
        }
    }
}

// ---------------------------------------------------------------------------
// Big GEMM: out[M][4096] = A[M][3072] @ B[4096][3072]^T + bias
// Now 2 CTAs/SM for latency hiding (tensor pipe was 45.8% busy at 1 CTA/SM).
// ---------------------------------------------------------------------------
#define GEMM_SMEM 40960

__device__ __forceinline__ void gemm_prefetch(uint32_t sb, int s,
    const __nv_bfloat16* __restrict__ A, const __nv_bfloat16* __restrict__ B,
    int m0, int n0, int k0, int tid)
{
    #pragma unroll
    for (int u = 0; u < 2; u++) {
        int unit = u * 256 + tid;
        int r = unit >> 2, c = unit & 3;
        cp16(sb + s * 20480 + r * 80 + c * 16, A + (size_t)(m0 + r) * KC3 + k0 + c * 8);
        cp16(sb + s * 20480 + 10240 + r * 80 + c * 16, B + (size_t)(n0 + r) * KC3 + k0 + c * 8);
    }
}

__global__ __launch_bounds__(256, 2) void gemm_cat(
    const __nv_bfloat16* __restrict__ A, const __nv_bfloat16* __restrict__ B,
    const float* __restrict__ bW, const float* __restrict__ bR,
    float* __restrict__ out)
{
    extern __shared__ char smem[];
    const uint32_t sb = s2u(smem);
    const int tid = threadIdx.x, lane = tid & 31, w = tid >> 5;
    const int wm = w & 3, wn = w >> 2;
    const int m0 = blockIdx.y * 128, n0 = blockIdx.x * 128;

    float acc[2][8][4];
    #pragma unroll
    for (int i = 0; i < 2; i++)
        #pragma unroll
        for (int j = 0; j < 8; j++)
            #pragma unroll
            for (int q = 0; q < 4; q++) acc[i][j][q] = 0.f;

    gemm_prefetch(sb, 0, A, B, m0, n0, 0, tid); CP_COMMIT();
    gemm_prefetch(sb, 1, A, B, m0, n0, 32, tid); CP_COMMIT();

    for (int it = 0; it < 96; it++) {
        CP_WAIT1();
        __syncthreads();
        const int s = it & 1;
        const uint32_t ab = sb + s * 20480;
        const uint32_t bb = ab + 10240;
        #pragma unroll
        for (int kk = 0; kk < 2; kk++) {
            uint32_t af[2][4], bf[4][4];
            #pragma unroll
            for (int mh = 0; mh < 2; mh++) {
                int row = wm * 32 + mh * 16 + ((lane >> 3) & 1) * 8 + (lane & 7);
                int ch = kk * 2 + (lane >> 4);
                ldsm_x4(af[mh], ab + row * 80 + ch * 16);
            }
            #pragma unroll
            for (int p = 0; p < 4; p++) {
                int g = lane >> 3;
                int row = wn * 64 + p * 16 + (g >> 1) * 8 + (lane & 7);
                int ch = kk * 2 + (g & 1);
                ldsm_x4(bf[p], bb + row * 80 + ch * 16);
            }
            #pragma unroll
            for (int mh = 0; mh < 2; mh++)
                #pragma unroll
                for (int p = 0; p < 4; p++) {
                    mma16816(acc[mh][p * 2],     af[mh], &bf[p][0]);
                    mma16816(acc[mh][p * 2 + 1], af[mh], &bf[p][2]);
                }
        }
        __syncthreads();
        if (it + 2 < 96) gemm_prefetch(sb, s, A, B, m0, n0, (it + 2) * 32, tid);
        CP_COMMIT();
    }

    #pragma unroll
    for (int mh = 0; mh < 2; mh++)
        #pragma unroll
        for (int nj = 0; nj < 8; nj++) {
            int row = m0 + wm * 32 + mh * 16 + (lane >> 2);
            int col = n0 + wn * 64 + nj * 8 + 2 * (lane & 3);
            float b0 = bW[col] + bR[col];
            float b1 = bW[col + 1] + bR[col + 1];
            float2 v0 = make_float2(acc[mh][nj][0] + b0, acc[mh][nj][1] + b1);
            float2 v1 = make_float2(acc[mh][nj][2] + b0, acc[mh][nj][3] + b1);
            *reinterpret_cast<float2*>(out + (size_t)row * G4 + col) = v0;
            *reinterpret_cast<float2*>(out + (size_t)(row + 8) * G4 + col) = v1;
        }
}

// ---------------------------------------------------------------------------
// Persistent recurrence v4 (fp16 2-term): 128 blocks x 256 threads.
// Critical path per step: poll -> y load (single 64KB cp.async wave) -> mma ->
// exchange -> pointwise -> y16 store -> fence -> release.
// yout/ycat/cn stores moved AFTER the release (not consumed by other blocks).
// smem: Rh 64K | Rl 64K | y 64K | gs 32x33 f32
// ---------------------------------------------------------------------------
#define PS_RH 0
#define PS_RL 65536
#define PS_Y  131072
#define PS_GS 196608
#define PS_SMEM (196608 + 4224)

__global__ __launch_bounds__(256) void lstm_persist(
    const float* __restrict__ gates,
    const __half* __restrict__ Rh, const __half* __restrict__ Rl,
    __half* __restrict__ y16,                 // [2][BH]
    const float* __restrict__ c0p,
    float* __restrict__ yout, long ystride,   // ystride==0 -> only write t==TT-1
    __nv_bfloat16* __restrict__ ycat,
    float* __restrict__ cnp)
{
    extern __shared__ char smem[];
    const uint32_t sb = s2u(smem);
    const int tid = threadIdx.x, lane = tid & 31, w = tid >> 5;
    const int blk = blockIdx.x;
    const int mh = w >> 2, cg = w & 3;

    // replay-safe monotonic flag base
    unsigned base = 0;
    if (tid < 128) base = ld_acq(&g_yflag[tid]);

    const int b_pw = tid >> 3, hl_pw = tid & 7;
    const int h_pw = blk * 8 + hl_pw;
    float creg = c0p[b_pw * HH + h_pw];

    // Load resident R slice: 32 rows x 1024 fp16, hi + lo, swizzled 16B chunks
    #pragma unroll 4
    for (int u = 0; u < 32; u++) {
        int unit = u * 256 + tid;            // 0..8191
        int s = unit >> 12, rem = unit & 4095;
        int r = rem >> 7, cc = rem & 127;
        const __half* src = (s ? Rl : Rh) + (size_t)(blk * 32 + r) * HH + cc * 8;
        uint4 v = *reinterpret_cast<const uint4*>(src);
        *reinterpret_cast<uint4*>(smem + (s ? PS_RL : PS_RH)
                                  + r * 2048 + ((cc ^ (r & 7)) * 16)) = v;
    }

    float* gs = reinterpret_cast<float*>(smem + PS_GS);
    const float INV = 1.f / 2048.f;

    for (int t = 0; t < TT; t++) {
        // gate-x prefetch (independent of y[t]) before the poll
        const float* gx = gates + (size_t)t * BB * G4 + (size_t)b_pw * G4;
        float gi = gx[h_pw], gf = gx[1024 + h_pw], gg = gx[2048 + h_pw], go = gx[3072 + h_pw];

        // wait for y[t] (parallel 128-flag acquire poll)
        if (tid < 128) {
            const unsigned tgt = base + (unsigned)t;
            while ((int)(ld_acq(&g_yflag[tid]) - tgt) < 0) {}
        }
        __syncthreads();

        // single-wave y load: 64 KB, 16 cp.async per thread
        const __half* yg = y16 + (size_t)(t & 1) * BH;
        #pragma unroll
        for (int u = 0; u < 16; u++) {
            int unit = u * 256 + tid;        // 0..4095
            int r = unit >> 7, cc = unit & 127;
            cp16(sb + PS_Y + r * 2048 + ((cc ^ (r & 7)) * 16),
                 yg + (size_t)r * HH + cc * 8);
        }
        CP_COMMIT();
        CP_WAIT0();
        __syncthreads();

        float accH[4] = {0.f, 0.f, 0.f, 0.f};
        float accL[4] = {0.f, 0.f, 0.f, 0.f};
        #pragma unroll 4
        for (int kl2 = 0; kl2 < 32; kl2++) {
            uint32_t bh4[4], bl4[4], a4[4];
            {
                int r = cg * 8 + (lane & 7);
                int cc = (kl2 * 4 + (lane >> 3)) ^ (r & 7);
                ldsm_x4(bh4, sb + PS_RH + r * 2048 + cc * 16);
                ldsm_x4(bl4, sb + PS_RL + r * 2048 + cc * 16);
            }
            #pragma unroll
            for (int j = 0; j < 2; j++) {
                int kl = kl2 * 2 + j;
                int row = mh * 16 + ((lane >> 3) & 1) * 8 + (lane & 7);
                int cc = (kl * 2 + (lane >> 4)) ^ (row & 7);
                ldsm_x4(a4, sb + PS_Y + row * 2048 + cc * 16);
                mma16816h(accH, a4, &bh4[j * 2]);
                mma16816h(accL, a4, &bl4[j * 2]);
            }
        }

        // exchange D[32b x 32col] through smem
        {
            int c0 = cg * 8 + 2 * (lane & 3);
            int b0 = mh * 16 + (lane >> 2);
            gs[c0 * 33 + b0]           = accH[0] + accL[0] * INV;
            gs[(c0 + 1) * 33 + b0]     = accH[1] + accL[1] * INV;
            gs[c0 * 33 + b0 + 8]       = accH[2] + accL[2] * INV;
            gs[(c0 + 1) * 33 + b0 + 8] = accH[3] + accL[3] * INV;
        }
        __syncthreads();

        // fused cell update (1 cell/thread)
        float vi = gi + gs[hl_pw * 33 + b_pw];
        float vf = gf + gs[(8 + hl_pw) * 33 + b_pw];
        float vg = gg + gs[(16 + hl_pw) * 33 + b_pw];
        float vo = go + gs[(24 + hl_pw) * 33 + b_pw];
        float ig = fsig(vi), fg = fsig(vf), og = fsig(vo);
        float zg = ftanh(vg);
        creg = fg * creg + ig * zg;
        float yn = og * ftanh(creg);

        // critical-path store: only the 2-byte fp16 next-y
        y16[(size_t)((t + 1) & 1) * BH + b_pw * HH + h_pw] = __float2half(yn);
        __threadfence();
        __syncthreads();
        if (tid == 0) st_rel(&g_yflag[blk], base + (unsigned)t + 1u);

        // off-critical-path outputs
        if (ystride != 0 || t == TT - 1)
            yout[(size_t)t * ystride + b_pw * HH + h_pw] = yn;
        if (ycat) {
            __nv_bfloat16 yhv = __float2bfloat16(yn);
            __nv_bfloat16 ylv = __float2bfloat16(yn - __bfloat162float(yhv));
            __nv_bfloat16* d = ycat + (size_t)t * BB * KC3 + (size_t)b_pw * KC3 + h_pw;
            d[0] = yhv; d[1024] = yhv; d[2048] = ylv;
        }
        if (t == TT - 1) cnp[b_pw * HH + h_pw] = creg;
    }
}

// ---------------------------------------------------------------------------
extern "C" void kernel_launch(void* const* d_in, const int* in_sizes, int n_in,
                              void* d_out, int out_size)
{
    const float* x   = (const float*)d_in[0];
    const float* h0  = (const float*)d_in[1];
    const float* c0  = (const float*)d_in[2];
    const float* W0  = (const float*)d_in[3];
    const float* R0  = (const float*)d_in[4];
    const float* bW0 = (const float*)d_in[5];
    const float* bR0 = (const float*)d_in[6];
    const float* W1  = (const float*)d_in[7];
    const float* R1  = (const float*)d_in[8];
    const float* bW1 = (const float*)d_in[9];
    const float* bR1 = (const float*)d_in[10];

    float* y2 = (float*)d_out;
    float* hn = y2 + (size_t)TT * BH;
    float* cn = hn + 2 * BH;

    float *gates, *yf;
    __half *y16, *R0h, *R0l, *R1h, *R1l;
    __nv_bfloat16 *xcat, *ycat, *w0c, *w1c;
    cudaGetSymbolAddress((void**)&gates, g_gates);
    cudaGetSymbolAddress((void**)&yf,    g_yf);
    cudaGetSymbolAddress((void**)&y16,   g_y16);
    cudaGetSymbolAddress((void**)&xcat,  g_xcat);
    cudaGetSymbolAddress((void**)&ycat,  g_ycat);
    cudaGetSymbolAddress((void**)&w0c,   g_w0cat);
    cudaGetSymbolAddress((void**)&w1c,   g_w1cat);
    cudaGetSymbolAddress((void**)&R0h,   g_R0h);
    cudaGetSymbolAddress((void**)&R0l,   g_R0l);
    cudaGetSymbolAddress((void**)&R1h,   g_R1h);
    cudaGetSymbolAddress((void**)&R1l,   g_R1l);

    cudaFuncSetAttribute(gemm_cat, cudaFuncAttributeMaxDynamicSharedMemorySize, GEMM_SMEM);
    cudaFuncSetAttribute(lstm_persist, cudaFuncAttributeMaxDynamicSharedMemorySize, PS_SMEM);

    const size_t bhBytes = (size_t)BH * sizeof(float);
    const dim3 ggrid(G4 / 128, (TT * BB) / 128);

    // ---- layer 0 ----
    split_cat<<<2048, 256>>>(x, xcat, (size_t)TT * BB, 0);
    split_cat<<<2048, 256>>>(W0, w0c, (size_t)G4, 1);
    split_R16<<<2080, 256>>>(R0, R0h, R0l, h0, y16);                  // +h0[0]->buf0
    gemm_cat<<<ggrid, 256, GEMM_SMEM>>>(xcat, w0c, bW0, bR0, gates);
    lstm_persist<<<128, 256, PS_SMEM>>>(gates, R0h, R0l, y16,
                                        c0, yf, 0, ycat, cn);

    // ---- layer 1 ----
    split_cat<<<2048, 256>>>(W1, w1c, (size_t)G4, 1);
    split_R16<<<2080, 256>>>(R1, R1h, R1l, h0 + BH, y16);             // +h0[1]->buf0
    gemm_cat<<<ggrid, 256, GEMM_SMEM>>>(ycat, w1c, bW1, bR1, gates);
    lstm_persist<<<128, 256, PS_SMEM>>>(gates, R1h, R1l, y16,
                                        c0 + BH, y2, BH, (__nv_bfloat16*)nullptr, cn + BH);

    // ---- epilogue copies ----
    cudaMemcpyAsync(hn, yf, bhBytes, cudaMemcpyDeviceToDevice);
    cudaMemcpyAsync(hn + BH, y2 + (size_t)(TT - 1) * BH, bhBytes, cudaMemcpyDeviceToDevice);
}

// round 8
// speedup vs baseline: 1.7541x; 1.7541x over previous
#include <cuda_runtime.h>
#include <cuda_bf16.h>
#include <cuda_fp16.h>
#include <cstdint>
#include <math.h>

#define TT 256
#define BB 32
#define HH 1024
#define G4 4096
#define BH (BB*HH)
#define KC3 3072

// ---------------------------------------------------------------------------
// Static scratch (no cudaMalloc allowed)
// ---------------------------------------------------------------------------
__device__ __align__(16) float g_gates[(size_t)TT*BB*G4];          // 128 MB
__device__ __align__(16) float g_yf[BH];
__device__ __align__(16) __half g_y16[2][BH];                      // y fp16 double buffer
__device__ __align__(16) __nv_bfloat16 g_xcat[(size_t)TT*BB*KC3];
__device__ __align__(16) __nv_bfloat16 g_ycat[(size_t)TT*BB*KC3];
__device__ __align__(16) __nv_bfloat16 g_w0cat[(size_t)G4*KC3];
__device__ __align__(16) __nv_bfloat16 g_w1cat[(size_t)G4*KC3];
__device__ __align__(16) __half g_R0h[(size_t)G4*HH];              // blk-reordered fp16
__device__ __align__(16) __half g_R1h[(size_t)G4*HH];

// per-block step flags (monotonic across launches/replays -> replay-safe)
__device__ unsigned g_yflag[128];

// ---------------------------------------------------------------------------
// PTX helpers (family-generic legal)
// ---------------------------------------------------------------------------
__device__ __forceinline__ uint32_t s2u(const void* p) {
    uint32_t a;
    asm("{ .reg .u64 t; cvta.to.shared.u64 t, %1; cvt.u32.u64 %0, t; }" : "=r"(a) : "l"(p));
    return a;
}
__device__ __forceinline__ void cp16(uint32_t saddr, const void* g) {
    asm volatile("cp.async.cg.shared.global [%0], [%1], 16;" :: "r"(saddr), "l"(g));
}
#define CP_COMMIT() asm volatile("cp.async.commit_group;" ::: "memory")
#define CP_WAIT1()  asm volatile("cp.async.wait_group 1;" ::: "memory")
#define CP_WAIT0()  asm volatile("cp.async.wait_group 0;" ::: "memory")

__device__ __forceinline__ void ldsm_x4(uint32_t* r, uint32_t addr) {
    asm volatile("ldmatrix.sync.aligned.m8n8.x4.shared.b16 {%0,%1,%2,%3}, [%4];"
        : "=r"(r[0]), "=r"(r[1]), "=r"(r[2]), "=r"(r[3]) : "r"(addr));
}
__device__ __forceinline__ void mma16816(float* d, const uint32_t* a, const uint32_t* b) {
    asm volatile("mma.sync.aligned.m16n8k16.row.col.f32.bf16.bf16.f32 "
        "{%0,%1,%2,%3}, {%4,%5,%6,%7}, {%8,%9}, {%0,%1,%2,%3};"
        : "+f"(d[0]), "+f"(d[1]), "+f"(d[2]), "+f"(d[3])
        : "r"(a[0]), "r"(a[1]), "r"(a[2]), "r"(a[3]), "r"(b[0]), "r"(b[1]));
}
__device__ __forceinline__ void mma16816h(float* d, const uint32_t* a, const uint32_t* b) {
    asm volatile("mma.sync.aligned.m16n8k16.row.col.f32.f16.f16.f32 "
        "{%0,%1,%2,%3}, {%4,%5,%6,%7}, {%8,%9}, {%0,%1,%2,%3};"
        : "+f"(d[0]), "+f"(d[1]), "+f"(d[2]), "+f"(d[3])
        : "r"(a[0]), "r"(a[1]), "r"(a[2]), "r"(a[3]), "r"(b[0]), "r"(b[1]));
}
__device__ __forceinline__ unsigned ld_acq(const unsigned* p) {
    unsigned v;
    asm volatile("ld.acquire.gpu.global.u32 %0, [%1];" : "=r"(v) : "l"(p));
    return v;
}
__device__ __forceinline__ void st_rel(unsigned* p, unsigned v) {
    asm volatile("st.release.gpu.global.u32 [%0], %1;" :: "l"(p), "r"(v));
}
__device__ __forceinline__ float fsig(float x) {
    return __fdividef(1.f, 1.f + __expf(-x));
}
__device__ __forceinline__ float ftanh(float x) {
    float e = __expf(-2.f * fabsf(x));
    float t = __fdividef(1.f - e, 1.f + e);
    return copysignf(t, x);
}

// ---------------------------------------------------------------------------
// Conversions
// ---------------------------------------------------------------------------
__global__ void split_cat(const float* __restrict__ src, __nv_bfloat16* __restrict__ dst,
                          size_t rows, int modeB) {
    size_t n = rows * HH;
    for (size_t i = (size_t)blockIdx.x * blockDim.x + threadIdx.x; i < n;
         i += (size_t)gridDim.x * blockDim.x) {
        size_t r = i >> 10; int k = (int)(i & 1023);
        float v = src[i];
        __nv_bfloat16 h = __float2bfloat16(v);
        __nv_bfloat16 l = __float2bfloat16(v - __bfloat162float(h));
        __nv_bfloat16* d = dst + r * KC3 + k;
        d[0] = h;
        d[1024] = modeB ? l : h;
        d[2048] = modeB ? h : l;
    }
}

// Reorder R to fp16 (dst row d = blk*32 + gate*8 + hl) and, in extra blocks,
// convert h0 slice into the fp16 y buffer 0.
__global__ void split_R16(const float* __restrict__ R, __half* __restrict__ hi,
                          const float* __restrict__ h0p, __half* __restrict__ y0) {
    if (blockIdx.x < 2048) {
        size_t base = (size_t)blockIdx.x * 2048 + threadIdx.x;
        #pragma unroll
        for (int u = 0; u < 8; u++) {
            size_t i = base + (size_t)u * 256;
            int d = (int)(i >> 10), k = (int)(i & 1023);
            int blk = d >> 5, gate = (d >> 3) & 3, hl = d & 7;
            int srow = gate * HH + blk * 8 + hl;
            hi[i] = __float2half(R[(size_t)srow * HH + k]);
        }
    } else {
        int base = (int)(blockIdx.x - 2048) * 1024 + threadIdx.x;
        #pragma unroll
        for (int u = 0; u < 4; u++) {
            int i = base + u * 256;
            y0[i] = __float2half(h0p[i]);
        }
    }
}

// ---------------------------------------------------------------------------
// Big GEMM: out[M][4096] = A[M][3072] @ B[4096][3072]^T + bias (2 CTAs/SM)
// ---------------------------------------------------------------------------
#define GEMM_SMEM 40960

__device__ __forceinline__ void gemm_prefetch(uint32_t sb, int s,
    const __nv_bfloat16* __restrict__ A, const __nv_bfloat16* __restrict__ B,
    int m0, int n0, int k0, int tid)
{
    #pragma unroll
    for (int u = 0; u < 2; u++) {
        int unit = u * 256 + tid;
        int r = unit >> 2, c = unit & 3;
        cp16(sb + s * 20480 + r * 80 + c * 16, A + (size_t)(m0 + r) * KC3 + k0 + c * 8);
        cp16(sb + s * 20480 + 10240 + r * 80 + c * 16, B + (size_t)(n0 + r) * KC3 + k0 + c * 8);
    }
}

__global__ __launch_bounds__(256, 2) void gemm_cat(
    const __nv_bfloat16* __restrict__ A, const __nv_bfloat16* __restrict__ B,
    const float* __restrict__ bW, const float* __restrict__ bR,
    float* __restrict__ out)
{
    extern __shared__ char smem[];
    const uint32_t sb = s2u(smem);
    const int tid = threadIdx.x, lane = tid & 31, w = tid >> 5;
    const int wm = w & 3, wn = w >> 2;
    const int m0 = blockIdx.y * 128, n0 = blockIdx.x * 128;

    float acc[2][8][4];
    #pragma unroll
    for (int i = 0; i < 2; i++)
        #pragma unroll
        for (int j = 0; j < 8; j++)
            #pragma unroll
            for (int q = 0; q < 4; q++) acc[i][j][q] = 0.f;

    gemm_prefetch(sb, 0, A, B, m0, n0, 0, tid); CP_COMMIT();
    gemm_prefetch(sb, 1, A, B, m0, n0, 32, tid); CP_COMMIT();

    for (int it = 0; it < 96; it++) {
        CP_WAIT1();
        __syncthreads();
        const int s = it & 1;
        const uint32_t ab = sb + s * 20480;
        const uint32_t bb = ab + 10240;
        #pragma unroll
        for (int kk = 0; kk < 2; kk++) {
            uint32_t af[2][4], bf[4][4];
            #pragma unroll
            for (int mh = 0; mh < 2; mh++) {
                int row = wm * 32 + mh * 16 + ((lane >> 3) & 1) * 8 + (lane & 7);
                int ch = kk * 2 + (lane >> 4);
                ldsm_x4(af[mh], ab + row * 80 + ch * 16);
            }
            #pragma unroll
            for (int p = 0; p < 4; p++) {
                int g = lane >> 3;
                int row = wn * 64 + p * 16 + (g >> 1) * 8 + (lane & 7);
                int ch = kk * 2 + (g & 1);
                ldsm_x4(bf[p], bb + row * 80 + ch * 16);
            }
            #pragma unroll
            for (int mh = 0; mh < 2; mh++)
                #pragma unroll
                for (int p = 0; p < 4; p++) {
                    mma16816(acc[mh][p * 2],     af[mh], &bf[p][0]);
                    mma16816(acc[mh][p * 2 + 1], af[mh], &bf[p][2]);
                }
        }
        __syncthreads();
        if (it + 2 < 96) gemm_prefetch(sb, s, A, B, m0, n0, (it + 2) * 32, tid);
        CP_COMMIT();
    }

    #pragma unroll
    for (int mh = 0; mh < 2; mh++)
        #pragma unroll
        for (int nj = 0; nj < 8; nj++) {
            int row = m0 + wm * 32 + mh * 16 + (lane >> 2);
            int col = n0 + wn * 64 + nj * 8 + 2 * (lane & 3);
            float b0 = bW[col] + bR[col];
            float b1 = bW[col + 1] + bR[col + 1];
            float2 v0 = make_float2(acc[mh][nj][0] + b0, acc[mh][nj][1] + b1);
            float2 v1 = make_float2(acc[mh][nj][2] + b0, acc[mh][nj][3] + b1);
            *reinterpret_cast<float2*>(out + (size_t)row * G4 + col) = v0;
            *reinterpret_cast<float2*>(out + (size_t)(row + 8) * G4 + col) = v1;
        }
}

// ---------------------------------------------------------------------------
// Persistent recurrence v5 (fp16 single-term R): 128 blocks x 256 threads.
// Block owns 32 reordered R rows (8 h x 4 gates) x K=1024, fp16, 64 KB smem.
// y loaded in two 32 KB double-buffered chunks (overlap load with mma).
// Critical path per step: poll -> y chunks -> mma -> exchange -> pointwise ->
// y16 store -> release (st.release only; no threadfence).
// smem: Rh 64K | y 2x32K | gs 32x33 f32
// ---------------------------------------------------------------------------
#define PS_RH 0
#define PS_Y(buf) (65536 + (buf)*32768)
#define PS_GS 131072
#define PS_SMEM (131072 + 4224)

__device__ __forceinline__ void pref_y16(uint32_t sb, int dbuf, int ch,
                                         const __half* __restrict__ y, int tid)
{
    #pragma unroll
    for (int u = 0; u < 8; u++) {
        int unit = u * 256 + tid;            // 0..2047
        int r = unit >> 6, cc = unit & 63;
        cp16(sb + PS_Y(dbuf) + r * 1024 + ((cc ^ (r & 7)) * 16),
             y + (size_t)r * HH + ch * 512 + cc * 8);
    }
}

__global__ __launch_bounds__(256) void lstm_persist(
    const float* __restrict__ gates,
    const __half* __restrict__ Rh,
    __half* __restrict__ y16,                 // [2][BH]
    const float* __restrict__ c0p,
    float* __restrict__ yout, long ystride,   // ystride==0 -> only write t==TT-1
    __nv_bfloat16* __restrict__ ycat,
    float* __restrict__ cnp)
{
    extern __shared__ char smem[];
    const uint32_t sb = s2u(smem);
    const int tid = threadIdx.x, lane = tid & 31, w = tid >> 5;
    const int blk = blockIdx.x;
    const int mh = w >> 2, cg = w & 3;

    // replay-safe monotonic flag base
    unsigned base = 0;
    if (tid < 128) base = ld_acq(&g_yflag[tid]);

    const int b_pw = tid >> 3, hl_pw = tid & 7;
    const int h_pw = blk * 8 + hl_pw;
    float creg = c0p[b_pw * HH + h_pw];

    // Load resident R slice: 32 rows x 1024 fp16, swizzled 16B chunks
    #pragma unroll 4
    for (int u = 0; u < 16; u++) {
        int unit = u * 256 + tid;            // 0..4095
        int r = unit >> 7, cc = unit & 127;
        const __half* src = Rh + (size_t)(blk * 32 + r) * HH + cc * 8;
        uint4 v = *reinterpret_cast<const uint4*>(src);
        *reinterpret_cast<uint4*>(smem + PS_RH + r * 2048 + ((cc ^ (r & 7)) * 16)) = v;
    }

    float* gs = reinterpret_cast<float*>(smem + PS_GS);

    for (int t = 0; t < TT; t++) {
        // gate-x prefetch (independent of y[t]) before the poll
        const float* gx = gates + (size_t)t * BB * G4 + (size_t)b_pw * G4;
        float gi = gx[h_pw], gf = gx[1024 + h_pw], gg = gx[2048 + h_pw], go = gx[3072 + h_pw];

        // wait for y[t] (parallel 128-flag acquire poll)
        if (tid < 128) {
            const unsigned tgt = base + (unsigned)t;
            while ((int)(ld_acq(&g_yflag[tid]) - tgt) < 0) {}
        }
        __syncthreads();

        const __half* yg = y16 + (size_t)(t & 1) * BH;
        pref_y16(sb, 0, 0, yg, tid); CP_COMMIT();
        pref_y16(sb, 1, 1, yg, tid); CP_COMMIT();

        float accH[4] = {0.f, 0.f, 0.f, 0.f};
        #pragma unroll
        for (int ch = 0; ch < 2; ch++) {
            if (ch == 0) CP_WAIT1(); else CP_WAIT0();
            __syncthreads();
            const uint32_t yb = sb + PS_Y(ch);
            #pragma unroll 4
            for (int kl2 = 0; kl2 < 16; kl2++) {
                uint32_t bh4[4], a4[4];
                {
                    int r = cg * 8 + (lane & 7);
                    int cc = (ch * 64 + kl2 * 4 + (lane >> 3)) ^ (r & 7);
                    ldsm_x4(bh4, sb + PS_RH + r * 2048 + cc * 16);
                }
                #pragma unroll
                for (int j = 0; j < 2; j++) {
                    int kl = kl2 * 2 + j;
                    int row = mh * 16 + ((lane >> 3) & 1) * 8 + (lane & 7);
                    int cc = (kl * 2 + (lane >> 4)) ^ (row & 7);
                    ldsm_x4(a4, yb + row * 1024 + cc * 16);
                    mma16816h(accH, a4, &bh4[j * 2]);
                }
            }
        }

        // exchange D[32b x 32col] through smem
        {
            int c0 = cg * 8 + 2 * (lane & 3);
            int b0 = mh * 16 + (lane >> 2);
            gs[c0 * 33 + b0]           = accH[0];
            gs[(c0 + 1) * 33 + b0]     = accH[1];
            gs[c0 * 33 + b0 + 8]       = accH[2];
            gs[(c0 + 1) * 33 + b0 + 8] = accH[3];
        }
        __syncthreads();

        // fused cell update (1 cell/thread)
        float vi = gi + gs[hl_pw * 33 + b_pw];
        float vf = gf + gs[(8 + hl_pw) * 33 + b_pw];
        float vg = gg + gs[(16 + hl_pw) * 33 + b_pw];
        float vo = go + gs[(24 + hl_pw) * 33 + b_pw];
        float ig = fsig(vi), fg = fsig(vf), og = fsig(vo);
        float zg = ftanh(vg);
        creg = fg * creg + ig * zg;
        float yn = og * ftanh(creg);

        // critical-path store: only the 2-byte fp16 next-y, then release.
        // st.release.gpu after __syncthreads gives the happens-before edge for
        // all 256 threads' y16 stores (barrier + release pattern).
        y16[(size_t)((t + 1) & 1) * BH + b_pw * HH + h_pw] = __float2half(yn);
        __syncthreads();
        if (tid == 0) st_rel(&g_yflag[blk], base + (unsigned)t + 1u);

        // off-critical-path outputs
        if (ystride != 0 || t == TT - 1)
            yout[(size_t)t * ystride + b_pw * HH + h_pw] = yn;
        if (ycat) {
            __nv_bfloat16 yhv = __float2bfloat16(yn);
            __nv_bfloat16 ylv = __float2bfloat16(yn - __bfloat162float(yhv));
            __nv_bfloat16* d = ycat + (size_t)t * BB * KC3 + (size_t)b_pw * KC3 + h_pw;
            d[0] = yhv; d[1024] = yhv; d[2048] = ylv;
        }
        if (t == TT - 1) cnp[b_pw * HH + h_pw] = creg;
    }
}

// ---------------------------------------------------------------------------
extern "C" void kernel_launch(void* const* d_in, const int* in_sizes, int n_in,
                              void* d_out, int out_size)
{
    const float* x   = (const float*)d_in[0];
    const float* h0  = (const float*)d_in[1];
    const float* c0  = (const float*)d_in[2];
    const float* W0  = (const float*)d_in[3];
    const float* R0  = (const float*)d_in[4];
    const float* bW0 = (const float*)d_in[5];
    const float* bR0 = (const float*)d_in[6];
    const float* W1  = (const float*)d_in[7];
    const float* R1  = (const float*)d_in[8];
    const float* bW1 = (const float*)d_in[9];
    const float* bR1 = (const float*)d_in[10];

    float* y2 = (float*)d_out;
    float* hn = y2 + (size_t)TT * BH;
    float* cn = hn + 2 * BH;

    float *gates, *yf;
    __half *y16, *R0h, *R1h;
    __nv_bfloat16 *xcat, *ycat, *w0c, *w1c;
    cudaGetSymbolAddress((void**)&gates, g_gates);
    cudaGetSymbolAddress((void**)&yf,    g_yf);
    cudaGetSymbolAddress((void**)&y16,   g_y16);
    cudaGetSymbolAddress((void**)&xcat,  g_xcat);
    cudaGetSymbolAddress((void**)&ycat,  g_ycat);
    cudaGetSymbolAddress((void**)&w0c,   g_w0cat);
    cudaGetSymbolAddress((void**)&w1c,   g_w1cat);
    cudaGetSymbolAddress((void**)&R0h,   g_R0h);
    cudaGetSymbolAddress((void**)&R1h,   g_R1h);

    cudaFuncSetAttribute(gemm_cat, cudaFuncAttributeMaxDynamicSharedMemorySize, GEMM_SMEM);
    cudaFuncSetAttribute(lstm_persist, cudaFuncAttributeMaxDynamicSharedMemorySize, PS_SMEM);

    const size_t bhBytes = (size_t)BH * sizeof(float);
    const dim3 ggrid(G4 / 128, (TT * BB) / 128);

    // ---- layer 0 ----
    split_cat<<<2048, 256>>>(x, xcat, (size_t)TT * BB, 0);
    split_cat<<<2048, 256>>>(W0, w0c, (size_t)G4, 1);
    split_R16<<<2080, 256>>>(R0, R0h, h0, y16);                       // +h0[0]->buf0
    gemm_cat<<<ggrid, 256, GEMM_SMEM>>>(xcat, w0c, bW0, bR0, gates);
    lstm_persist<<<128, 256, PS_SMEM>>>(gates, R0h, y16,
                                        c0, yf, 0, ycat, cn);

    // ---- layer 1 ----
    split_cat<<<2048, 256>>>(W1, w1c, (size_t)G4, 1);
    split_R16<<<2080, 256>>>(R1, R1h, h0 + BH, y16);                  // +h0[1]->buf0
    gemm_cat<<<ggrid, 256, GEMM_SMEM>>>(ycat, w1c, bW1, bR1, gates);
    lstm_persist<<<128, 256, PS_SMEM>>>(gates, R1h, y16,
                                        c0 + BH, y2, BH, (__nv_bfloat16*)nullptr, cn + BH);

    // ---- epilogue copies ----
    cudaMemcpyAsync(hn, yf, bhBytes, cudaMemcpyDeviceToDevice);
    cudaMemcpyAsync(hn + BH, y2 + (size_t)(TT - 1) * BH, bhBytes, cudaMemcpyDeviceToDevice);
}